// round 1
// baseline (speedup 1.0000x reference)
#include <cuda_runtime.h>
#include <cuda_bf16.h>

// FFReLU log-likelihood: out[r,n] = -0.5*(y[n]-mu[r,n])^2 - 0.5*log(2*pi)
//   mu[r,n] = sum_h w2[r,h] * relu( sum_i w1[r,h,i] * x[n,i] )
// Shapes: x[2048,13], y[2048,1], w[256,7168] (w1 = first 512*13, w2 = last 512)
// Output: float[256,2048]

#define H_DIM 512
#define IN_DIM 13
#define R_DIM 256
#define N_DIM 2048
#define W_DIM 7168
#define W1_SZ 6656          // 512*13
#define TN 128              // n-tile per block
#define TH 128              // h-chunk per iteration
#define NEG_HALF_LOG_2PI (-0.918938533204672741780329736406f)

// ---- packed f32x2 helpers (Blackwell FFMA2) ----
__device__ __forceinline__ void ffma2(unsigned long long& d,
                                      unsigned long long a,
                                      unsigned long long b) {
    asm("fma.rn.f32x2 %0, %1, %2, %0;" : "+l"(d) : "l"(a), "l"(b));
}
__device__ __forceinline__ unsigned long long pack2(float lo, float hi) {
    unsigned long long r;
    asm("mov.b64 %0, {%1, %2};" : "=l"(r) : "f"(lo), "f"(hi));
    return r;
}
__device__ __forceinline__ void unpack2(unsigned long long v, float& lo, float& hi) {
    asm("mov.b64 {%0, %1}, %2;" : "=f"(lo), "=f"(hi) : "l"(v));
}

__global__ __launch_bounds__(256, 2)
void ffrelu_kernel(const float* __restrict__ x,
                   const float* __restrict__ y,
                   const float* __restrict__ w,
                   float* __restrict__ out) {
    __shared__ __align__(16) float xs[IN_DIM][TN];   // x tile, k-major
    __shared__ __align__(16) float w1s[IN_DIM][TH];  // w1 chunk, k-major
    __shared__ float w2s[TH];
    __shared__ float red[16][129];                   // padded for conflict-free reduce

    const int tid = threadIdx.x;
    const int tc  = tid & 15;    // column group 0..15
    const int tr  = tid >> 4;    // row group 0..15
    const int n0  = blockIdx.x * TN;
    const int r   = blockIdx.y;

    // ---- stage x tile: 128 rows x 13 = 1664 contiguous floats ----
    {
        const float* xbase = x + (size_t)n0 * IN_DIM;
        for (int idx = tid; idx < TN * IN_DIM; idx += 256) {
            float v = xbase[idx];
            xs[idx % IN_DIM][idx / IN_DIM] = v;
        }
    }

    float mu[8];
#pragma unroll
    for (int c = 0; c < 8; c++) mu[c] = 0.f;

    const float* wr = w + (size_t)r * W_DIM;

#pragma unroll 1
    for (int hb = 0; hb < H_DIM / TH; hb++) {
        __syncthreads();  // also covers xs on first iteration
        // ---- stage w1 chunk (contiguous 1664 floats) + w2 chunk ----
        {
            const float* wbase = wr + hb * (TH * IN_DIM);
            for (int idx = tid; idx < TH * IN_DIM; idx += 256) {
                float v = wbase[idx];
                w1s[idx % IN_DIM][idx / IN_DIM] = v;
            }
            if (tid < TH) w2s[tid] = wr[W1_SZ + hb * TH + tid];
        }
        __syncthreads();

        // ---- 8h x 8n micro-tile GEMM over K=13, packed f32x2 ----
        unsigned long long acc[8][4];
#pragma unroll
        for (int j = 0; j < 8; j++)
#pragma unroll
            for (int c2 = 0; c2 < 4; c2++) acc[j][c2] = 0ull;

#pragma unroll
        for (int k = 0; k < IN_DIM; k++) {
            unsigned long long a2[8], b2[4];
#pragma unroll
            for (int j = 0; j < 8; j++) {
                float a = w1s[k][tr + j * 16];
                a2[j] = pack2(a, a);
            }
#pragma unroll
            for (int c2 = 0; c2 < 4; c2++) {
                b2[c2] = *reinterpret_cast<const unsigned long long*>(
                    &xs[k][2 * (tc + c2 * 16)]);
            }
#pragma unroll
            for (int j = 0; j < 8; j++)
#pragma unroll
                for (int c2 = 0; c2 < 4; c2++)
                    ffma2(acc[j][c2], a2[j], b2[c2]);
        }

        // ---- relu + w2-weighted fold into mu ----
#pragma unroll
        for (int j = 0; j < 8; j++) {
            float w2v = w2s[tr + j * 16];
#pragma unroll
            for (int c2 = 0; c2 < 4; c2++) {
                float s0, s1;
                unpack2(acc[j][c2], s0, s1);
                mu[2 * c2]     = fmaf(w2v, fmaxf(s0, 0.f), mu[2 * c2]);
                mu[2 * c2 + 1] = fmaf(w2v, fmaxf(s1, 0.f), mu[2 * c2 + 1]);
            }
        }
    }

    // ---- cross-thread (tr) reduction of mu partials ----
    __syncthreads();
#pragma unroll
    for (int c2 = 0; c2 < 4; c2++) {
        int col = 2 * (tc + c2 * 16);
        red[tr][col]     = mu[2 * c2];
        red[tr][col + 1] = mu[2 * c2 + 1];
    }
    __syncthreads();

    if (tid < TN) {
        float s = 0.f;
#pragma unroll
        for (int t = 0; t < 16; t++) s += red[t][tid];
        float resid = y[n0 + tid] - s;
        out[(size_t)r * N_DIM + n0 + tid] =
            fmaf(-0.5f * resid, resid, NEG_HALF_LOG_2PI);
    }
}

extern "C" void kernel_launch(void* const* d_in, const int* in_sizes, int n_in,
                              void* d_out, int out_size) {
    const float* x = (const float*)d_in[0];   // [2048, 13]
    const float* y = (const float*)d_in[1];   // [2048, 1]
    const float* w = (const float*)d_in[2];   // [256, 7168]
    float* out = (float*)d_out;               // [256, 2048]

    dim3 grid(N_DIM / TN, R_DIM);             // 16 x 256
    dim3 block(256);
    ffrelu_kernel<<<grid, block>>>(x, y, w, out);
}

// round 2
// speedup vs baseline: 1.1016x; 1.1016x over previous
#include <cuda_runtime.h>
#include <cuda_bf16.h>

// FFReLU log-likelihood: out[r,n] = -0.5*(y[n]-mu[r,n])^2 - 0.5*log(2*pi)
//   mu[r,n] = sum_h w2[r,h] * relu( sum_i w1[r,h,i] * x[n,i] )
// x[2048,13], y[2048,1], w[256,7168] (w1 = 512*13, w2 = 512) -> out float[256,2048]

#define H_DIM 512
#define IN_DIM 13
#define R_DIM 256
#define N_DIM 2048
#define W_DIM 7168
#define W1_SZ 6656
#define TN 128
#define TH 128
#define CHUNK_F (TH * IN_DIM)   // 1664 floats per w1 chunk
#define NEG_HALF_LOG_2PI (-0.918938533204672741780329736406f)

typedef unsigned long long ull;

__device__ __forceinline__ void ffma2(ull& d, ull a, ull b) {
    asm("fma.rn.f32x2 %0, %1, %2, %0;" : "+l"(d) : "l"(a), "l"(b));
}
__device__ __forceinline__ ull pack2(float lo, float hi) {
    ull r;
    asm("mov.b64 %0, {%1, %2};" : "=l"(r) : "f"(lo), "f"(hi));
    return r;
}
__device__ __forceinline__ void unpack2(ull v, float& lo, float& hi) {
    asm("mov.b64 {%0, %1}, %2;" : "=f"(lo), "=f"(hi) : "l"(v));
}

__global__ __launch_bounds__(256, 2)
void ffrelu_kernel(const float* __restrict__ x,
                   const float* __restrict__ y,
                   const float* __restrict__ w,
                   float* __restrict__ out) {
    // k-major tiles; h (resp. n) contiguous in the row -> float4 loads
    __shared__ __align__(16) float xs[IN_DIM][TN];        // x tile
    __shared__ __align__(16) float w1s[2][IN_DIM][TH];    // double-buffered w1 chunk
    __shared__ __align__(16) float w2s[H_DIM];
    __shared__ __align__(16) float red[16][TN + 4];       // cross-thread mu reduce

    const int tid = threadIdx.x;
    const int tc  = tid & 15;        // n-group: columns tc*8 .. tc*8+7
    const int tr  = tid >> 4;        // h-group: rows    tr*8 .. tr*8+7
    const int n0  = tc * 8;
    const int h0  = tr * 8;
    const int nblk = blockIdx.x * TN;
    const int r   = blockIdx.y;

    const float* wr = w + (size_t)r * W_DIM;

    // ---- stage x tile (1664 contiguous floats, transposed to k-major) ----
    {
        const float* xbase = x + (size_t)nblk * IN_DIM;
        for (int idx = tid; idx < TN * IN_DIM; idx += 256)
            xs[idx % IN_DIM][idx / IN_DIM] = xbase[idx];
    }
    // ---- stage all of w2 (512 floats) ----
    w2s[tid]       = wr[W1_SZ + tid];
    w2s[tid + 256] = wr[W1_SZ + 256 + tid];
    // ---- stage w1 chunk 0 ----
    for (int idx = tid; idx < CHUNK_F; idx += 256)
        w1s[0][idx % IN_DIM][idx / IN_DIM] = wr[idx];
    __syncthreads();

    float mu[8];
#pragma unroll
    for (int c = 0; c < 8; c++) mu[c] = 0.f;

#pragma unroll 1
    for (int hb = 0; hb < H_DIM / TH; hb++) {
        const int buf = hb & 1;

        // ---- prefetch next w1 chunk into registers ----
        float pf[7];
        if (hb < 3) {
            const float* wbase = wr + (hb + 1) * CHUNK_F;
#pragma unroll
            for (int i = 0; i < 7; i++) {
                int idx = tid + i * 256;
                pf[i] = (idx < CHUNK_F) ? wbase[idx] : 0.f;
            }
        }

        // ---- 8h x 8n micro-tile, h-pair accumulators ----
        ull acc[4][8];
#pragma unroll
        for (int hp = 0; hp < 4; hp++)
#pragma unroll
            for (int n = 0; n < 8; n++) acc[hp][n] = 0ull;

#pragma unroll
        for (int k = 0; k < IN_DIM; k++) {
            const float4 a03 = *reinterpret_cast<const float4*>(&w1s[buf][k][h0]);
            const float4 a47 = *reinterpret_cast<const float4*>(&w1s[buf][k][h0 + 4]);
            const float4 b03 = *reinterpret_cast<const float4*>(&xs[k][n0]);
            const float4 b47 = *reinterpret_cast<const float4*>(&xs[k][n0 + 4]);
            ull ap[4];
            ap[0] = pack2(a03.x, a03.y);
            ap[1] = pack2(a03.z, a03.w);
            ap[2] = pack2(a47.x, a47.y);
            ap[3] = pack2(a47.z, a47.w);
            ull bd[8];
            bd[0] = pack2(b03.x, b03.x);
            bd[1] = pack2(b03.y, b03.y);
            bd[2] = pack2(b03.z, b03.z);
            bd[3] = pack2(b03.w, b03.w);
            bd[4] = pack2(b47.x, b47.x);
            bd[5] = pack2(b47.y, b47.y);
            bd[6] = pack2(b47.z, b47.z);
            bd[7] = pack2(b47.w, b47.w);
#pragma unroll
            for (int hp = 0; hp < 4; hp++)
#pragma unroll
                for (int n = 0; n < 8; n++)
                    ffma2(acc[hp][n], ap[hp], bd[n]);
        }

        // ---- relu + w2-weighted fold into mu ----
        const int hg = hb * TH + h0;
#pragma unroll
        for (int hp = 0; hp < 4; hp++) {
            const float2 w2p = *reinterpret_cast<const float2*>(&w2s[hg + 2 * hp]);
#pragma unroll
            for (int n = 0; n < 8; n++) {
                float s0, s1;
                unpack2(acc[hp][n], s0, s1);
                mu[n] = fmaf(w2p.x, fmaxf(s0, 0.f), mu[n]);
                mu[n] = fmaf(w2p.y, fmaxf(s1, 0.f), mu[n]);
            }
        }

        // ---- store prefetched chunk into the other buffer ----
        if (hb < 3) {
#pragma unroll
            for (int i = 0; i < 7; i++) {
                int idx = tid + i * 256;
                if (idx < CHUNK_F)
                    w1s[buf ^ 1][idx % IN_DIM][idx / IN_DIM] = pf[i];
            }
        }
        __syncthreads();
    }

    // ---- cross-thread (tr) reduction of mu partials ----
#pragma unroll
    for (int n = 0; n < 8; n += 2)
        *reinterpret_cast<float2*>(&red[tr][n0 + n]) = make_float2(mu[n], mu[n + 1]);
    __syncthreads();

    if (tid < TN) {
        float s = 0.f;
#pragma unroll
        for (int t = 0; t < 16; t++) s += red[t][tid];
        float resid = y[nblk + tid] - s;
        out[(size_t)r * N_DIM + nblk + tid] =
            fmaf(-0.5f * resid, resid, NEG_HALF_LOG_2PI);
    }
}

extern "C" void kernel_launch(void* const* d_in, const int* in_sizes, int n_in,
                              void* d_out, int out_size) {
    const float* x = (const float*)d_in[0];
    const float* y = (const float*)d_in[1];
    const float* w = (const float*)d_in[2];
    float* out = (float*)d_out;

    dim3 grid(N_DIM / TN, R_DIM);   // 16 x 256
    dim3 block(256);
    ffrelu_kernel<<<grid, block>>>(x, y, w, out);
}

// round 4
// speedup vs baseline: 1.4423x; 1.3092x over previous
#include <cuda_runtime.h>
#include <cuda_bf16.h>

// FFReLU log-likelihood: out[r,n] = -0.5*(y[n]-mu[r,n])^2 - 0.5*log(2*pi)
//   mu[r,n] = sum_h w2[r,h] * relu( sum_i w1[r,h,i] * x[n,i] )
// x[2048,13], y[2048,1], w[256,7168] (w1 = 512*13, w2 = 512) -> out float[256,2048]

#define H_DIM 512
#define IN_DIM 13
#define R_DIM 256
#define N_DIM 2048
#define W_DIM 7168
#define W1_SZ 6656
#define TN 128
#define TH 128
#define XS_PITCH 144         // padded row for swizzled x tile
#define W1_PITCH 132         // padded row: bank = (4k+h)%32 on staging stores
#define RED_PITCH 132
#define CHUNK_F (TH * IN_DIM)   // 1664 floats per w1 chunk
#define NEG_HALF_LOG_2PI (-0.918938533204672741780329736406f)

typedef unsigned long long ull;

__device__ __forceinline__ void ffma2(ull& d, ull a, ull b) {
    asm("fma.rn.f32x2 %0, %1, %2, %0;" : "+l"(d) : "l"(a), "l"(b));
}
__device__ __forceinline__ ull pack2(float lo, float hi) {
    ull r;
    asm("mov.b64 %0, {%1, %2};" : "=l"(r) : "f"(lo), "f"(hi));
    return r;
}
__device__ __forceinline__ void unpack2(ull v, float& lo, float& hi) {
    asm("mov.b64 {%0, %1}, %2;" : "=f"(lo), "=f"(hi) : "l"(v));
}

// swizzled word offset for x tile column n: distinct bank-quads for stride-8 readers
__device__ __forceinline__ int xswz(int n) { return n + 4 * (n >> 5); }

__global__ __launch_bounds__(256, 2)
void ffrelu_kernel(const float* __restrict__ x,
                   const float* __restrict__ y,
                   const float* __restrict__ w,
                   float* __restrict__ out) {
    __shared__ __align__(16) float xs[IN_DIM][XS_PITCH];      // swizzled x tile
    __shared__ __align__(16) float w1s[2][IN_DIM][W1_PITCH];  // double-buffered w1
    __shared__ __align__(16) float w2s[H_DIM];
    __shared__ __align__(16) float red[16][RED_PITCH];

    const int tid = threadIdx.x;
    const int tc  = tid & 15;        // n-group: columns tc*8 .. tc*8+7
    const int tr  = tid >> 4;        // h-group: rows    tr*8 .. tr*8+7
    const int n0  = tc * 8;
    const int h0  = tr * 8;
    const int nblk = blockIdx.x * TN;
    const int r   = blockIdx.y;

    const int nA = xswz(n0);         // swizzled offsets (compile-time per thread)
    const int nB = xswz(n0 + 4);

    const float* wr = w + (size_t)r * W_DIM;

    // ---- stage x tile (swizzled) ----
    {
        const float* xbase = x + (size_t)nblk * IN_DIM;
        for (int idx = tid; idx < TN * IN_DIM; idx += 256)
            xs[idx % IN_DIM][xswz(idx / IN_DIM)] = xbase[idx];
    }
    // ---- stage all of w2 ----
    w2s[tid]       = wr[W1_SZ + tid];
    w2s[tid + 256] = wr[W1_SZ + 256 + tid];
    // ---- stage w1 chunk 0 ----
    for (int idx = tid; idx < CHUNK_F; idx += 256)
        w1s[0][idx % IN_DIM][idx / IN_DIM] = wr[idx];
    __syncthreads();

    float mu[8];
#pragma unroll
    for (int c = 0; c < 8; c++) mu[c] = 0.f;

#pragma unroll 1
    for (int hb = 0; hb < H_DIM / TH; hb++) {
        const int buf = hb & 1;

        // ---- prefetch next w1 chunk into registers ----
        float pf[7];
        if (hb < 3) {
            const float* wbase = wr + (hb + 1) * CHUNK_F;
#pragma unroll
            for (int i = 0; i < 7; i++) {
                int idx = tid + i * 256;
                pf[i] = (idx < CHUNK_F) ? wbase[idx] : 0.f;
            }
        }

        // ---- 8h x 8n micro-tile, h-pair accumulators ----
        ull acc[4][8];
#pragma unroll
        for (int hp = 0; hp < 4; hp++)
#pragma unroll
            for (int n = 0; n < 8; n++) acc[hp][n] = 0ull;

#pragma unroll
        for (int k = 0; k < IN_DIM; k++) {
            const float4 a03 = *reinterpret_cast<const float4*>(&w1s[buf][k][h0]);
            const float4 a47 = *reinterpret_cast<const float4*>(&w1s[buf][k][h0 + 4]);
            const float4 b03 = *reinterpret_cast<const float4*>(&xs[k][nA]);
            const float4 b47 = *reinterpret_cast<const float4*>(&xs[k][nB]);
            ull ap[4];
            ap[0] = pack2(a03.x, a03.y);
            ap[1] = pack2(a03.z, a03.w);
            ap[2] = pack2(a47.x, a47.y);
            ap[3] = pack2(a47.z, a47.w);
            ull bd[8];
            bd[0] = pack2(b03.x, b03.x);
            bd[1] = pack2(b03.y, b03.y);
            bd[2] = pack2(b03.z, b03.z);
            bd[3] = pack2(b03.w, b03.w);
            bd[4] = pack2(b47.x, b47.x);
            bd[5] = pack2(b47.y, b47.y);
            bd[6] = pack2(b47.z, b47.z);
            bd[7] = pack2(b47.w, b47.w);
#pragma unroll
            for (int hp = 0; hp < 4; hp++)
#pragma unroll
                for (int n = 0; n < 8; n++)
                    ffma2(acc[hp][n], ap[hp], bd[n]);
        }

        // ---- relu + w2-weighted fold into mu ----
        const int hg = hb * TH + h0;
#pragma unroll
        for (int hp = 0; hp < 4; hp++) {
            const float2 w2p = *reinterpret_cast<const float2*>(&w2s[hg + 2 * hp]);
#pragma unroll
            for (int n = 0; n < 8; n++) {
                float s0, s1;
                unpack2(acc[hp][n], s0, s1);
                mu[n] = fmaf(w2p.x, fmaxf(s0, 0.f), mu[n]);
                mu[n] = fmaf(w2p.y, fmaxf(s1, 0.f), mu[n]);
            }
        }

        // ---- store prefetched chunk into the other buffer ----
        if (hb < 3) {
#pragma unroll
            for (int i = 0; i < 7; i++) {
                int idx = tid + i * 256;
                if (idx < CHUNK_F)
                    w1s[buf ^ 1][idx % IN_DIM][idx / IN_DIM] = pf[i];
            }
        }
        __syncthreads();
    }

    // ---- cross-thread (tr) reduction of mu partials ----
#pragma unroll
    for (int n = 0; n < 8; n += 2)
        *reinterpret_cast<float2*>(&red[tr][n0 + n]) = make_float2(mu[n], mu[n + 1]);
    __syncthreads();

    if (tid < TN) {
        float s = 0.f;
#pragma unroll
        for (int t = 0; t < 16; t++) s += red[t][tid];
        float resid = y[nblk + tid] - s;
        out[(size_t)r * N_DIM + nblk + tid] =
            fmaf(-0.5f * resid, resid, NEG_HALF_LOG_2PI);
    }
}

extern "C" void kernel_launch(void* const* d_in, const int* in_sizes, int n_in,
                              void* d_out, int out_size) {
    const float* x = (const float*)d_in[0];
    const float* y = (const float*)d_in[1];
    const float* w = (const float*)d_in[2];
    float* out = (float*)d_out;

    dim3 grid(N_DIM / TN, R_DIM);   // 16 x 256
    dim3 block(256);
    ffrelu_kernel<<<grid, block>>>(x, y, w, out);
}

// round 8
// speedup vs baseline: 3.0717x; 2.1297x over previous
#include <cuda_runtime.h>
#include <cuda_bf16.h>
#include <cstdint>
#include <cstring>

// FFReLU loglik via baseline tensor-core mma.sync (HMMA, bf16 3-term split).
// out[r,n] = -0.5*(y[n]-mu[r,n])^2 - 0.5*log(2pi)
// mu[r,n] = sum_h w2[r,h]*relu(sum_k w1[r,h,k]*x[n,k])
// D[n][h] = x @ w1^T via mma.m16n8k16.row.col: A = x (row-major n x k),
// B^T = w1 (row-major h x k) == B col-major. K=16 covers IN_DIM=13 (zero pad).

#define IN_DIM 13
#define H_DIM 512
#define R_DIM 256
#define N_DIM 2048
#define W_DIM 7168
#define W1_SZ 6656
#define TN 256                 // n rows per block
#define PITCH 48               // smem row pitch (16 bf16 = 32B data + 16B pad) -> conflict-free
#define XHI_OFF 0
#define XLO_OFF (XHI_OFF + TN * PITCH)          // 12288
#define WHI_OFF (XLO_OFF + TN * PITCH)          // 24576
#define WLO_OFF (WHI_OFF + H_DIM * PITCH)       // 49152
#define W2_OFF  (WLO_OFF + H_DIM * PITCH)       // 73728
#define SMEM_TOTAL (W2_OFF + H_DIM * 4)         // 75776
#define NEG_HALF_LOG_2PI (-0.918938533204672741780329736406f)

__device__ __forceinline__ uint32_t smem_u32(const void* p) {
    uint32_t a;
    asm("{ .reg .u64 t; cvta.to.shared.u64 t, %1; cvt.u32.u64 %0, t; }" : "=r"(a) : "l"(p));
    return a;
}

__device__ __forceinline__ void ldm4(uint32_t r[4], uint32_t addr) {
    asm volatile("ldmatrix.sync.aligned.m8n8.x4.shared.b16 {%0,%1,%2,%3}, [%4];"
                 : "=r"(r[0]), "=r"(r[1]), "=r"(r[2]), "=r"(r[3]) : "r"(addr));
}

__device__ __forceinline__ void mma_bf16(float d[4], const uint32_t a[4],
                                         uint32_t b0, uint32_t b1) {
    asm volatile(
        "mma.sync.aligned.m16n8k16.row.col.f32.bf16.bf16.f32 "
        "{%0,%1,%2,%3}, {%4,%5,%6,%7}, {%8,%9}, {%0,%1,%2,%3};"
        : "+f"(d[0]), "+f"(d[1]), "+f"(d[2]), "+f"(d[3])
        : "r"(a[0]), "r"(a[1]), "r"(a[2]), "r"(a[3]), "r"(b0), "r"(b1));
}

// Split a 13-float row into bf16 hi/lo tiles (k padded to 16 with zeros), STS.128 x4.
__device__ __forceinline__ void pack_row(char* smem, int hi_off, int lo_off,
                                         int row, const float* v) {
    uint32_t hi[8], lo[8];
#pragma unroll
    for (int p = 0; p < 8; p++) {
        float a0 = (2 * p < IN_DIM) ? v[2 * p] : 0.f;
        float a1 = (2 * p + 1 < IN_DIM) ? v[2 * p + 1] : 0.f;
        __nv_bfloat16 h0 = __float2bfloat16(a0), h1 = __float2bfloat16(a1);
        float r0 = a0 - __bfloat162float(h0);
        float r1 = a1 - __bfloat162float(h1);
        __nv_bfloat162 hp, lp;
        hp.x = h0; hp.y = h1;
        lp.x = __float2bfloat16(r0); lp.y = __float2bfloat16(r1);
        memcpy(&hi[p], &hp, 4);
        memcpy(&lo[p], &lp, 4);
    }
    char* hr = smem + hi_off + row * PITCH;
    ((uint4*)hr)[0] = make_uint4(hi[0], hi[1], hi[2], hi[3]);
    ((uint4*)hr)[1] = make_uint4(hi[4], hi[5], hi[6], hi[7]);
    char* lr = smem + lo_off + row * PITCH;
    ((uint4*)lr)[0] = make_uint4(lo[0], lo[1], lo[2], lo[3]);
    ((uint4*)lr)[1] = make_uint4(lo[4], lo[5], lo[6], lo[7]);
}

__global__ __launch_bounds__(128, 2)
void ffrelu_hmma_kernel(const float* __restrict__ x,
                        const float* __restrict__ y,
                        const float* __restrict__ w,
                        float* __restrict__ out) {
    extern __shared__ char smem[];
    const uint32_t sb = smem_u32(smem);
    const int tid = threadIdx.x;
    const int lane = tid & 31;
    const int wid = tid >> 5;            // warp 0..3, owns rows 64*wid..+63
    const int g8 = lane & 7;
    const int grp = lane >> 3;           // ldmatrix address group 0..3
    const int nblk = blockIdx.x * TN;
    const int r = blockIdx.y;
    const float* wr = w + (size_t)r * W_DIM;

    // ---- stage x tile: rows tid, tid+128 ----
#pragma unroll
    for (int i = 0; i < 2; i++) {
        const int row = tid + i * 128;
        const float* xr = x + (size_t)(nblk + row) * IN_DIM;
        float v[IN_DIM];
#pragma unroll
        for (int k = 0; k < IN_DIM; k++) v[k] = xr[k];
        pack_row(smem, XHI_OFF, XLO_OFF, row, v);
    }
    // ---- stage w1: rows tid + 128*i ----
#pragma unroll
    for (int i = 0; i < 4; i++) {
        const int h = tid + i * 128;
        const float* wrow = wr + h * IN_DIM;
        float v[IN_DIM];
#pragma unroll
        for (int k = 0; k < IN_DIM; k++) v[k] = wrow[k];
        pack_row(smem, WHI_OFF, WLO_OFF, h, v);
    }
    // ---- stage w2 ----
#pragma unroll
    for (int i = 0; i < 4; i++)
        ((float*)(smem + W2_OFF))[tid + 128 * i] = wr[W1_SZ + tid + 128 * i];
    __syncthreads();

    // ---- A fragments (x) once per warp: 4 m16-tiles, hi+lo ----
    // A tile order: t0 rows0-7/off0, t1 rows8-15/off0, t2 rows0-7/off16, t3 rows8-15/off16
    uint32_t a_hi[4][4], a_lo[4][4];
#pragma unroll
    for (int mt = 0; mt < 4; mt++) {
        uint32_t aaddr = sb + XHI_OFF +
            (64 * wid + 16 * mt + (grp & 1) * 8 + g8) * PITCH + (grp >> 1) * 16;
        ldm4(a_hi[mt], aaddr);
        ldm4(a_lo[mt], aaddr + (XLO_OFF - XHI_OFF));
    }

    // B tile order per 16-h double-chunk: t0 n0-7/off0, t1 n0-7/off16, t2 n8-15/off0, t3 n8-15/off16
    uint32_t bHi = sb + WHI_OFF + ((grp >> 1) * 8 + g8) * PITCH + (grp & 1) * 16;
    uint32_t bLo = bHi + (WLO_OFF - WHI_OFF);

    float mu[4][2];
#pragma unroll
    for (int mt = 0; mt < 4; mt++) { mu[mt][0] = 0.f; mu[mt][1] = 0.f; }

    const int c4 = lane & 3;

#pragma unroll 1
    for (int dc = 0; dc < H_DIM / 16; dc++) {      // 32 double-chunks of 16 h
        uint32_t bh[4], bl[4];
        ldm4(bh, bHi);
        ldm4(bl, bLo);
        bHi += 16 * PITCH;
        bLo += 16 * PITCH;
#pragma unroll
        for (int half = 0; half < 2; half++) {
            const float2 w2p = *(const float2*)(smem + W2_OFF +
                                (dc * 16 + half * 8 + 2 * c4) * 4);
            const uint32_t b0h = bh[2 * half], b1h = bh[2 * half + 1];
            const uint32_t b0l = bl[2 * half], b1l = bl[2 * half + 1];
#pragma unroll
            for (int mt = 0; mt < 4; mt++) {
                float d[4] = {0.f, 0.f, 0.f, 0.f};
                mma_bf16(d, a_hi[mt], b0h, b1h);   // hi*hi
                mma_bf16(d, a_lo[mt], b0h, b1h);   // x_lo*w_hi
                mma_bf16(d, a_hi[mt], b0l, b1l);   // x_hi*w_lo
                mu[mt][0] = fmaf(w2p.x, fmaxf(d[0], 0.f), mu[mt][0]);
                mu[mt][0] = fmaf(w2p.y, fmaxf(d[1], 0.f), mu[mt][0]);
                mu[mt][1] = fmaf(w2p.x, fmaxf(d[2], 0.f), mu[mt][1]);
                mu[mt][1] = fmaf(w2p.y, fmaxf(d[3], 0.f), mu[mt][1]);
            }
        }
    }

    // ---- butterfly over the 4 col-threads (lane%4) ----
#pragma unroll
    for (int mt = 0; mt < 4; mt++)
#pragma unroll
        for (int i = 0; i < 2; i++) {
            float v = mu[mt][i];
            v += __shfl_xor_sync(0xffffffffu, v, 1);
            v += __shfl_xor_sync(0xffffffffu, v, 2);
            mu[mt][i] = v;
        }

    // lane (g, c): store Mtile mt == c, rows g and g+8
    const int g = lane >> 2;
    const float m0 = (c4 == 0) ? mu[0][0] : (c4 == 1) ? mu[1][0]
                   : (c4 == 2) ? mu[2][0] : mu[3][0];
    const float m1 = (c4 == 0) ? mu[0][1] : (c4 == 1) ? mu[1][1]
                   : (c4 == 2) ? mu[2][1] : mu[3][1];
    const int n = nblk + 64 * wid + 16 * c4 + g;
    {
        const float r0 = y[n] - m0;
        out[(size_t)r * N_DIM + n] = fmaf(-0.5f * r0, r0, NEG_HALF_LOG_2PI);
        const float r1 = y[n + 8] - m1;
        out[(size_t)r * N_DIM + n + 8] = fmaf(-0.5f * r1, r1, NEG_HALF_LOG_2PI);
    }
}

extern "C" void kernel_launch(void* const* d_in, const int* in_sizes, int n_in,
                              void* d_out, int out_size) {
    const float* x = (const float*)d_in[0];   // [2048,13]
    const float* y = (const float*)d_in[1];   // [2048,1]
    const float* w = (const float*)d_in[2];   // [256,7168]
    float* out = (float*)d_out;               // [256,2048]

    cudaFuncSetAttribute(ffrelu_hmma_kernel,
                         cudaFuncAttributeMaxDynamicSharedMemorySize, SMEM_TOTAL);
    dim3 grid(N_DIM / TN, R_DIM);   // 8 x 256
    ffrelu_hmma_kernel<<<grid, 128, SMEM_TOTAL>>>(x, y, w, out);
}

// round 9
// speedup vs baseline: 3.9387x; 1.2823x over previous
#include <cuda_runtime.h>
#include <cuda_fp16.h>
#include <cstdint>
#include <cstring>

// FFReLU loglik via mma.sync m16n8k16 fp16 2-term split:
//   x = xh + xl (both fp16, ~22-bit combined), w1 as single fp16.
//   D = xh @ wh^T + xl @ wh^T   (dropped xh*wl ~ 2^-12 -> rel_err ~3e-4)
// out[r,n] = -0.5*(y[n]-mu)^2 - 0.5*log(2pi),  mu = sum_h w2*relu(D[n][h])

#define IN_DIM 13
#define H_DIM 512
#define R_DIM 256
#define N_DIM 2048
#define W_DIM 7168
#define W1_SZ 6656
#define TN 256
#define PITCH 48               // 16 fp16 = 32B data + 16B pad -> conflict-free ldmatrix/STS
#define XHI_OFF 0
#define XLO_OFF (XHI_OFF + TN * PITCH)          // 12288
#define WH_OFF  (XLO_OFF + TN * PITCH)          // 24576
#define W2_OFF  (WH_OFF + H_DIM * PITCH)        // 49152
#define SMEM_TOTAL (W2_OFF + H_DIM * 4)         // 51200
#define NEG_HALF_LOG_2PI (-0.918938533204672741780329736406f)

__device__ __forceinline__ uint32_t smem_u32(const void* p) {
    uint32_t a;
    asm("{ .reg .u64 t; cvta.to.shared.u64 t, %1; cvt.u32.u64 %0, t; }" : "=r"(a) : "l"(p));
    return a;
}

__device__ __forceinline__ void ldm4(uint32_t r[4], uint32_t addr) {
    asm volatile("ldmatrix.sync.aligned.m8n8.x4.shared.b16 {%0,%1,%2,%3}, [%4];"
                 : "=r"(r[0]), "=r"(r[1]), "=r"(r[2]), "=r"(r[3]) : "r"(addr));
}

__device__ __forceinline__ void mma_fp16(float d[4], const uint32_t a[4],
                                         uint32_t b0, uint32_t b1) {
    asm volatile(
        "mma.sync.aligned.m16n8k16.row.col.f32.f16.f16.f32 "
        "{%0,%1,%2,%3}, {%4,%5,%6,%7}, {%8,%9}, {%0,%1,%2,%3};"
        : "+f"(d[0]), "+f"(d[1]), "+f"(d[2]), "+f"(d[3])
        : "r"(a[0]), "r"(a[1]), "r"(a[2]), "r"(a[3]), "r"(b0), "r"(b1));
}

// x row -> fp16 hi + lo tiles (k padded to 16 with zeros)
__device__ __forceinline__ void pack_row_split(char* smem, int row, const float* v) {
    uint32_t hi[8], lo[8];
#pragma unroll
    for (int p = 0; p < 8; p++) {
        float a0 = (2 * p < IN_DIM) ? v[2 * p] : 0.f;
        float a1 = (2 * p + 1 < IN_DIM) ? v[2 * p + 1] : 0.f;
        __half h0 = __float2half_rn(a0), h1 = __float2half_rn(a1);
        float r0 = a0 - __half2float(h0);
        float r1 = a1 - __half2float(h1);
        __half2 hp, lp;
        hp.x = h0; hp.y = h1;
        lp.x = __float2half_rn(r0); lp.y = __float2half_rn(r1);
        memcpy(&hi[p], &hp, 4);
        memcpy(&lo[p], &lp, 4);
    }
    char* hr = smem + XHI_OFF + row * PITCH;
    ((uint4*)hr)[0] = make_uint4(hi[0], hi[1], hi[2], hi[3]);
    ((uint4*)hr)[1] = make_uint4(hi[4], hi[5], hi[6], hi[7]);
    char* lr = smem + XLO_OFF + row * PITCH;
    ((uint4*)lr)[0] = make_uint4(lo[0], lo[1], lo[2], lo[3]);
    ((uint4*)lr)[1] = make_uint4(lo[4], lo[5], lo[6], lo[7]);
}

// w row -> single fp16 tile
__device__ __forceinline__ void pack_row_single(char* smem, int row, const float* v) {
    uint32_t hi[8];
#pragma unroll
    for (int p = 0; p < 8; p++) {
        float a0 = (2 * p < IN_DIM) ? v[2 * p] : 0.f;
        float a1 = (2 * p + 1 < IN_DIM) ? v[2 * p + 1] : 0.f;
        __half2 hp;
        hp.x = __float2half_rn(a0); hp.y = __float2half_rn(a1);
        memcpy(&hi[p], &hp, 4);
    }
    char* hr = smem + WH_OFF + row * PITCH;
    ((uint4*)hr)[0] = make_uint4(hi[0], hi[1], hi[2], hi[3]);
    ((uint4*)hr)[1] = make_uint4(hi[4], hi[5], hi[6], hi[7]);
}

__global__ __launch_bounds__(128, 3)
void ffrelu_hmma_kernel(const float* __restrict__ x,
                        const float* __restrict__ y,
                        const float* __restrict__ w,
                        float* __restrict__ out) {
    extern __shared__ char smem[];
    const uint32_t sb = smem_u32(smem);
    const int tid = threadIdx.x;
    const int lane = tid & 31;
    const int wid = tid >> 5;            // warp owns n-rows 64*wid..+63
    const int g8 = lane & 7;
    const int grp = lane >> 3;
    const int nblk = blockIdx.x * TN;
    const int r = blockIdx.y;
    const float* wr = w + (size_t)r * W_DIM;

    // ---- stage x tile (rows tid, tid+128): fp16 hi+lo ----
#pragma unroll
    for (int i = 0; i < 2; i++) {
        const int row = tid + i * 128;
        const float* xr = x + (size_t)(nblk + row) * IN_DIM;
        float v[IN_DIM];
#pragma unroll
        for (int k = 0; k < IN_DIM; k++) v[k] = xr[k];
        pack_row_split(smem, row, v);
    }
    // ---- stage w1 (4 rows/thread): single fp16 ----
#pragma unroll
    for (int i = 0; i < 4; i++) {
        const int h = tid + i * 128;
        const float* wrow = wr + h * IN_DIM;
        float v[IN_DIM];
#pragma unroll
        for (int k = 0; k < IN_DIM; k++) v[k] = wrow[k];
        pack_row_single(smem, h, v);
    }
    // ---- stage w2 ----
#pragma unroll
    for (int i = 0; i < 4; i++)
        ((float*)(smem + W2_OFF))[tid + 128 * i] = wr[W1_SZ + tid + 128 * i];
    __syncthreads();

    // ---- A fragments once per warp: 4 m16-tiles, hi+lo ----
    uint32_t a_hi[4][4], a_lo[4][4];
#pragma unroll
    for (int mt = 0; mt < 4; mt++) {
        uint32_t aaddr = sb + XHI_OFF +
            (64 * wid + 16 * mt + (grp & 1) * 8 + g8) * PITCH + (grp >> 1) * 16;
        ldm4(a_hi[mt], aaddr);
        ldm4(a_lo[mt], aaddr + (XLO_OFF - XHI_OFF));
    }

    // B: per 16-h chunk, x4 ldmatrix: t0(h0-7,k0-7) t1(h0-7,k8-15) t2(h8-15,k0-7) t3(h8-15,k8-15)
    uint32_t bAddr = sb + WH_OFF + ((grp >> 1) * 8 + g8) * PITCH + (grp & 1) * 16;

    float mu[4][2];
#pragma unroll
    for (int mt = 0; mt < 4; mt++) { mu[mt][0] = 0.f; mu[mt][1] = 0.f; }

    const int c4 = lane & 3;

    // software-pipelined B loads
    uint32_t bcur[4];
    ldm4(bcur, bAddr);
    bAddr += 16 * PITCH;

#pragma unroll 1
    for (int dc = 0; dc < H_DIM / 16; dc++) {
        uint32_t bnxt[4];
        if (dc < H_DIM / 16 - 1) {
            ldm4(bnxt, bAddr);
            bAddr += 16 * PITCH;
        }
#pragma unroll
        for (int half = 0; half < 2; half++) {
            const float2 w2p = *(const float2*)(smem + W2_OFF +
                                (dc * 16 + half * 8 + 2 * c4) * 4);
            const uint32_t b0 = bcur[2 * half], b1 = bcur[2 * half + 1];
#pragma unroll
            for (int mt = 0; mt < 4; mt++) {
                float d[4] = {0.f, 0.f, 0.f, 0.f};
                mma_fp16(d, a_hi[mt], b0, b1);   // xh * wh
                mma_fp16(d, a_lo[mt], b0, b1);   // xl * wh
                mu[mt][0] = fmaf(w2p.x, fmaxf(d[0], 0.f), mu[mt][0]);
                mu[mt][0] = fmaf(w2p.y, fmaxf(d[1], 0.f), mu[mt][0]);
                mu[mt][1] = fmaf(w2p.x, fmaxf(d[2], 0.f), mu[mt][1]);
                mu[mt][1] = fmaf(w2p.y, fmaxf(d[3], 0.f), mu[mt][1]);
            }
        }
#pragma unroll
        for (int i = 0; i < 4; i++) bcur[i] = bnxt[i];
    }

    // ---- butterfly over the 4 col-threads ----
#pragma unroll
    for (int mt = 0; mt < 4; mt++)
#pragma unroll
        for (int i = 0; i < 2; i++) {
            float v = mu[mt][i];
            v += __shfl_xor_sync(0xffffffffu, v, 1);
            v += __shfl_xor_sync(0xffffffffu, v, 2);
            mu[mt][i] = v;
        }

    const int g = lane >> 2;
    const float m0 = (c4 == 0) ? mu[0][0] : (c4 == 1) ? mu[1][0]
                   : (c4 == 2) ? mu[2][0] : mu[3][0];
    const float m1 = (c4 == 0) ? mu[0][1] : (c4 == 1) ? mu[1][1]
                   : (c4 == 2) ? mu[2][1] : mu[3][1];
    const int n = nblk + 64 * wid + 16 * c4 + g;
    {
        const float r0 = y[n] - m0;
        out[(size_t)r * N_DIM + n] = fmaf(-0.5f * r0, r0, NEG_HALF_LOG_2PI);
        const float r1 = y[n + 8] - m1;
        out[(size_t)r * N_DIM + n + 8] = fmaf(-0.5f * r1, r1, NEG_HALF_LOG_2PI);
    }
}

extern "C" void kernel_launch(void* const* d_in, const int* in_sizes, int n_in,
                              void* d_out, int out_size) {
    const float* x = (const float*)d_in[0];   // [2048,13]
    const float* y = (const float*)d_in[1];   // [2048,1]
    const float* w = (const float*)d_in[2];   // [256,7168]
    float* out = (float*)d_out;               // [256,2048]

    cudaFuncSetAttribute(ffrelu_hmma_kernel,
                         cudaFuncAttributeMaxDynamicSharedMemorySize, SMEM_TOTAL);
    dim3 grid(N_DIM / TN, R_DIM);   // 8 x 256
    ffrelu_hmma_kernel<<<grid, 128, SMEM_TOTAL>>>(x, y, w, out);
}

// round 10
// speedup vs baseline: 5.9028x; 1.4986x over previous
#include <cuda_runtime.h>
#include <cuda_fp16.h>
#include <cstdint>
#include <cstring>

// FFReLU loglik via mma.sync m16n8k16, single fp16 term (x and w both fp16).
// Dropped terms x*w_lo and x_lo*w ~2^-12 each -> rel_err ~3.3e-4 (< 1e-3).
// Fold uses packed fma.rn.f32x2 for the w2-weighted h-reduction.
// out[r,n] = -0.5*(y[n]-mu)^2 - 0.5*log(2pi),  mu = sum_h w2*relu(D[n][h])

#define IN_DIM 13
#define H_DIM 512
#define R_DIM 256
#define N_DIM 2048
#define W_DIM 7168
#define W1_SZ 6656
#define TN 256
#define PITCH 48               // 16 fp16 = 32B data + 16B pad -> conflict-free
#define XH_OFF 0
#define WH_OFF (XH_OFF + TN * PITCH)            // 12288
#define W2_OFF (WH_OFF + H_DIM * PITCH)         // 36864
#define SMEM_TOTAL (W2_OFF + H_DIM * 4)         // 38912
#define NEG_HALF_LOG_2PI (-0.918938533204672741780329736406f)

typedef unsigned long long ull;

__device__ __forceinline__ uint32_t smem_u32(const void* p) {
    uint32_t a;
    asm("{ .reg .u64 t; cvta.to.shared.u64 t, %1; cvt.u32.u64 %0, t; }" : "=r"(a) : "l"(p));
    return a;
}

__device__ __forceinline__ void ldm4(uint32_t r[4], uint32_t addr) {
    asm volatile("ldmatrix.sync.aligned.m8n8.x4.shared.b16 {%0,%1,%2,%3}, [%4];"
                 : "=r"(r[0]), "=r"(r[1]), "=r"(r[2]), "=r"(r[3]) : "r"(addr));
}

__device__ __forceinline__ void mma_fp16(float d[4], const uint32_t a[4],
                                         uint32_t b0, uint32_t b1) {
    asm volatile(
        "mma.sync.aligned.m16n8k16.row.col.f32.f16.f16.f32 "
        "{%0,%1,%2,%3}, {%4,%5,%6,%7}, {%8,%9}, {%0,%1,%2,%3};"
        : "+f"(d[0]), "+f"(d[1]), "+f"(d[2]), "+f"(d[3])
        : "r"(a[0]), "r"(a[1]), "r"(a[2]), "r"(a[3]), "r"(b0), "r"(b1));
}

__device__ __forceinline__ void ffma2(ull& d, ull a, ull b) {
    asm("fma.rn.f32x2 %0, %1, %2, %0;" : "+l"(d) : "l"(a), "l"(b));
}
__device__ __forceinline__ ull pack2(float lo, float hi) {
    ull r;
    asm("mov.b64 %0, {%1, %2};" : "=l"(r) : "f"(lo), "f"(hi));
    return r;
}
__device__ __forceinline__ void unpack2(ull v, float& lo, float& hi) {
    asm("mov.b64 {%0, %1}, %2;" : "=f"(lo), "=f"(hi) : "l"(v));
}

// row of 13 floats -> single fp16 tile row (k padded to 16 with zeros)
__device__ __forceinline__ void pack_row(char* smem, int off, int row, const float* v) {
    uint32_t hi[8];
#pragma unroll
    for (int p = 0; p < 8; p++) {
        float a0 = (2 * p < IN_DIM) ? v[2 * p] : 0.f;
        float a1 = (2 * p + 1 < IN_DIM) ? v[2 * p + 1] : 0.f;
        __half2 hp;
        hp.x = __float2half_rn(a0); hp.y = __float2half_rn(a1);
        memcpy(&hi[p], &hp, 4);
    }
    char* hr = smem + off + row * PITCH;
    ((uint4*)hr)[0] = make_uint4(hi[0], hi[1], hi[2], hi[3]);
    ((uint4*)hr)[1] = make_uint4(hi[4], hi[5], hi[6], hi[7]);
}

__global__ __launch_bounds__(128, 4)
void ffrelu_hmma_kernel(const float* __restrict__ x,
                        const float* __restrict__ y,
                        const float* __restrict__ w,
                        float* __restrict__ out) {
    extern __shared__ char smem[];
    const uint32_t sb = smem_u32(smem);
    const int tid = threadIdx.x;
    const int lane = tid & 31;
    const int wid = tid >> 5;            // warp owns n-rows 64*wid..+63
    const int g8 = lane & 7;
    const int grp = lane >> 3;
    const int nblk = blockIdx.x * TN;
    const int r = blockIdx.y;
    const float* wr = w + (size_t)r * W_DIM;

    // ---- stage x tile (rows tid, tid+128) ----
#pragma unroll
    for (int i = 0; i < 2; i++) {
        const int row = tid + i * 128;
        const float* xr = x + (size_t)(nblk + row) * IN_DIM;
        float v[IN_DIM];
#pragma unroll
        for (int k = 0; k < IN_DIM; k++) v[k] = xr[k];
        pack_row(smem, XH_OFF, row, v);
    }
    // ---- stage w1 (4 rows/thread) ----
#pragma unroll
    for (int i = 0; i < 4; i++) {
        const int h = tid + i * 128;
        const float* wrow = wr + h * IN_DIM;
        float v[IN_DIM];
#pragma unroll
        for (int k = 0; k < IN_DIM; k++) v[k] = wrow[k];
        pack_row(smem, WH_OFF, h, v);
    }
    // ---- stage w2 ----
#pragma unroll
    for (int i = 0; i < 4; i++)
        ((float*)(smem + W2_OFF))[tid + 128 * i] = wr[W1_SZ + tid + 128 * i];
    __syncthreads();

    // ---- A fragments once per warp: 4 m16-tiles ----
    uint32_t a_hi[4][4];
#pragma unroll
    for (int mt = 0; mt < 4; mt++) {
        uint32_t aaddr = sb + XH_OFF +
            (64 * wid + 16 * mt + (grp & 1) * 8 + g8) * PITCH + (grp >> 1) * 16;
        ldm4(a_hi[mt], aaddr);
    }

    // B: per 16-h chunk, x4 ldmatrix
    uint32_t bAddr = sb + WH_OFF + ((grp >> 1) * 8 + g8) * PITCH + (grp & 1) * 16;

    ull mu2[4][2];
#pragma unroll
    for (int mt = 0; mt < 4; mt++) { mu2[mt][0] = 0ull; mu2[mt][1] = 0ull; }

    const int c4 = lane & 3;

    // software-pipelined B loads
    uint32_t bcur[4];
    ldm4(bcur, bAddr);
    bAddr += 16 * PITCH;

#pragma unroll 1
    for (int dc = 0; dc < H_DIM / 16; dc++) {
        uint32_t bnxt[4];
        if (dc < H_DIM / 16 - 1) {
            ldm4(bnxt, bAddr);
            bAddr += 16 * PITCH;
        }
#pragma unroll
        for (int half = 0; half < 2; half++) {
            const float2 w2p = *(const float2*)(smem + W2_OFF +
                                (dc * 16 + half * 8 + 2 * c4) * 4);
            const ull w2pair = pack2(w2p.x, w2p.y);
            const uint32_t b0 = bcur[2 * half], b1 = bcur[2 * half + 1];
#pragma unroll
            for (int mt = 0; mt < 4; mt++) {
                float d[4] = {0.f, 0.f, 0.f, 0.f};
                mma_fp16(d, a_hi[mt], b0, b1);
                ffma2(mu2[mt][0], w2pair, pack2(fmaxf(d[0], 0.f), fmaxf(d[1], 0.f)));
                ffma2(mu2[mt][1], w2pair, pack2(fmaxf(d[2], 0.f), fmaxf(d[3], 0.f)));
            }
        }
#pragma unroll
        for (int i = 0; i < 4; i++) bcur[i] = bnxt[i];
    }

    // ---- horizontal add of the f32x2 pairs + butterfly over 4 col-threads ----
    float mu[4][2];
#pragma unroll
    for (int mt = 0; mt < 4; mt++)
#pragma unroll
        for (int i = 0; i < 2; i++) {
            float lo, hi;
            unpack2(mu2[mt][i], lo, hi);
            float v = lo + hi;
            v += __shfl_xor_sync(0xffffffffu, v, 1);
            v += __shfl_xor_sync(0xffffffffu, v, 2);
            mu[mt][i] = v;
        }

    const int g = lane >> 2;
    const float m0 = (c4 == 0) ? mu[0][0] : (c4 == 1) ? mu[1][0]
                   : (c4 == 2) ? mu[2][0] : mu[3][0];
    const float m1 = (c4 == 0) ? mu[0][1] : (c4 == 1) ? mu[1][1]
                   : (c4 == 2) ? mu[2][1] : mu[3][1];
    const int n = nblk + 64 * wid + 16 * c4 + g;
    {
        const float r0 = y[n] - m0;
        out[(size_t)r * N_DIM + n] = fmaf(-0.5f * r0, r0, NEG_HALF_LOG_2PI);
        const float r1 = y[n + 8] - m1;
        out[(size_t)r * N_DIM + n + 8] = fmaf(-0.5f * r1, r1, NEG_HALF_LOG_2PI);
    }
}

extern "C" void kernel_launch(void* const* d_in, const int* in_sizes, int n_in,
                              void* d_out, int out_size) {
    const float* x = (const float*)d_in[0];   // [2048,13]
    const float* y = (const float*)d_in[1];   // [2048,1]
    const float* w = (const float*)d_in[2];   // [256,7168]
    float* out = (float*)d_out;               // [256,2048]

    cudaFuncSetAttribute(ffrelu_hmma_kernel,
                         cudaFuncAttributeMaxDynamicSharedMemorySize, SMEM_TOTAL);
    dim3 grid(N_DIM / TN, R_DIM);   // 8 x 256
    ffrelu_hmma_kernel<<<grid, 128, SMEM_TOTAL>>>(x, y, w, out);
}